// round 6
// baseline (speedup 1.0000x reference)
#include <cuda_runtime.h>
#include <cstdint>

#define S_LEN 1024
#define DM 256
#define NH 8
#define DU 32
#define NT 16               // S_LEN / 64
#define TEMPC 0.078125f     // TEMP / (2*DU) = 5/64

// ---------------- scratch (no allocations allowed) ----------------
__device__ float g_Q[S_LEN * DM];
__device__ float g_K[S_LEN * DM];
__device__ float g_V[S_LEN * DM];
__device__ float g_O[S_LEN * DM];
__device__ float g_sumK[NH * S_LEN];
__device__ float g_pnum[NT * NH * S_LEN * DU];   // [jt][h][i][d]
__device__ float g_pden[NT * NH * S_LEN];        // [jt][h][i]

// ---------------- packed f32x2 helpers (FADD2 / FFMA2) ----------------
__device__ __forceinline__ uint64_t f32x2_add(uint64_t a, uint64_t b) {
    uint64_t d; asm("add.rn.f32x2 %0, %1, %2;" : "=l"(d) : "l"(a), "l"(b)); return d;
}
__device__ __forceinline__ uint64_t f32x2_fma(uint64_t a, uint64_t b, uint64_t c) {
    uint64_t d; asm("fma.rn.f32x2 %0, %1, %2, %3;" : "=l"(d) : "l"(a), "l"(b), "l"(c)); return d;
}
__device__ __forceinline__ uint64_t f32x2_pack(float x, float y) {
    uint64_t d; asm("mov.b64 %0, {%1, %2};" : "=l"(d) : "f"(x), "f"(y)); return d;
}
__device__ __forceinline__ float2 f32x2_unpack(uint64_t a) {
    float2 r; asm("mov.b64 {%0, %1}, %2;" : "=f"(r.x), "=f"(r.y) : "l"(a)); return r;
}

// ---------------- 32x64-tile fp32 GEMM body (FFMA2, zero-MOV inner loop) ----
// C[row,col] = act( A[S_LEN,DM] @ W[DM,DM] + b ).  Per-thread 2m x 4n.
// A stored duplicated (float2{a,a}) so packed-n FFMA2 needs no register packing.
// If sumk != nullptr, also writes per-row sums of the (sigmoid) outputs,
// one head (=32 cols) per half of the 64-col tile.
__device__ __forceinline__ void gemm_body(const float* __restrict__ A,
                                          const float* __restrict__ W,
                                          const float* __restrict__ b,
                                          float* __restrict__ C,
                                          bool sig, float* __restrict__ sumk,
                                          int bm, int bn)
{
    __shared__ __align__(16) float2 Astd[32][33];  // [k][m] duplicated, padded
    __shared__ __align__(16) float  Ws[32][64];    // [k][n]
    __shared__ float ssum[32][17];                 // row-sum partials (K only)

    const int tid = threadIdx.x;
    const int tx = tid & 15;        // n = tx*4 .. +3
    const int ty = tid >> 4;        // m = ty*2, ty*2+1

    uint64_t c2[2][2];              // [m][npair], lanes = (n0,n1)
    c2[0][0] = c2[0][1] = c2[1][0] = c2[1][1] = 0;

    for (int k0 = 0; k0 < DM; k0 += 32) {
        {   // A tile: 32 rows x 32 k, transposed+duplicated
            int m = tid >> 3;
            int kc = (tid & 7) << 2;
            float4 v = *(const float4*)&A[(bm * 32 + m) * DM + k0 + kc];
            Astd[kc + 0][m] = make_float2(v.x, v.x);
            Astd[kc + 1][m] = make_float2(v.y, v.y);
            Astd[kc + 2][m] = make_float2(v.z, v.z);
            Astd[kc + 3][m] = make_float2(v.w, v.w);
        }
#pragma unroll
        for (int l = 0; l < 2; l++) {   // W tile 32 x 64
            int f = tid + l * 256;
            int k = f >> 4;
            int nc = (f & 15) << 2;
            *(float4*)&Ws[k][nc] = *(const float4*)&W[(k0 + k) * DM + bn * 64 + nc];
        }
        __syncthreads();
#pragma unroll
        for (int k = 0; k < 32; k++) {
            uint64_t a0 = *(const uint64_t*)&Astd[k][ty * 2];      // LDS.64 dup
            uint64_t a1 = *(const uint64_t*)&Astd[k][ty * 2 + 1];
            ulonglong2 bp = *(const ulonglong2*)&Ws[k][tx * 4];    // LDS.128: 2 n-pairs
            c2[0][0] = f32x2_fma(bp.x, a0, c2[0][0]);
            c2[0][1] = f32x2_fma(bp.y, a0, c2[0][1]);
            c2[1][0] = f32x2_fma(bp.x, a1, c2[1][0]);
            c2[1][1] = f32x2_fma(bp.y, a1, c2[1][1]);
        }
        __syncthreads();
    }

    float4 bb = *(const float4*)&b[bn * 64 + tx * 4];
    float rs[2];
#pragma unroll
    for (int m = 0; m < 2; m++) {
        float2 p0 = f32x2_unpack(c2[m][0]);
        float2 p1 = f32x2_unpack(c2[m][1]);
        float t0 = p0.x + bb.x, t1 = p0.y + bb.y;
        float t2 = p1.x + bb.z, t3 = p1.y + bb.w;
        if (sig) {
            t0 = 1.0f / (1.0f + __expf(-t0));
            t1 = 1.0f / (1.0f + __expf(-t1));
            t2 = 1.0f / (1.0f + __expf(-t2));
            t3 = 1.0f / (1.0f + __expf(-t3));
        }
        rs[m] = (t0 + t1) + (t2 + t3);
        *(float4*)&C[(bm * 32 + ty * 2 + m) * DM + bn * 64 + tx * 4] =
            make_float4(t0, t1, t2, t3);
    }

    if (sumk) {   // per-row head sums (each tile half = one full head)
        ssum[ty * 2 + 0][tx] = rs[0];
        ssum[ty * 2 + 1][tx] = rs[1];
        __syncthreads();
        if (tid < 64) {
            int m = tid >> 1, half = tid & 1, base = half * 8;
            float s = 0.f;
#pragma unroll
            for (int x = 0; x < 8; x++) s += ssum[m][base + x];
            sumk[(bn * 2 + half) * S_LEN + bm * 32 + m] = s;
        }
    }
}

__global__ __launch_bounds__(256) void qkv_kernel(const float* __restrict__ x,
                                                  const float* __restrict__ Wq, const float* __restrict__ bq,
                                                  const float* __restrict__ Wk, const float* __restrict__ bk,
                                                  const float* __restrict__ Wv, const float* __restrict__ bv)
{
    int z = blockIdx.z;
    const float* W = (z == 0) ? Wq : ((z == 1) ? Wk : Wv);
    const float* b = (z == 0) ? bq : ((z == 1) ? bk : bv);
    float* C = (z == 0) ? g_Q : ((z == 1) ? g_K : g_V);
    gemm_body(x, W, b, C, z < 2, (z == 1) ? g_sumK : nullptr,
              blockIdx.x, blockIdx.y);
}

__global__ __launch_bounds__(256) void proj_kernel(const float* __restrict__ Wo,
                                                   const float* __restrict__ bo,
                                                   float* __restrict__ out)
{
    gemm_body(g_O, Wo, bo, out, false, nullptr, blockIdx.x, blockIdx.y);
}

// ---------------- attention tile kernel (packed f32x2) ----------------
// p_ij = exp( TEMPC * (sumK_j - sum_d |Q_id - K_jd|) ); row-const terms cancel.
// Grid.x enumerates the 136 lower-triangle (it,jt) tiles exactly.
__global__ __launch_bounds__(256) void attn_kernel()
{
    // decode triangular index -> (it, jt)
    int t = blockIdx.x;
    int it = (int)((sqrtf(8.0f * t + 1.0f) - 1.0f) * 0.5f);
    if ((it + 1) * (it + 2) / 2 <= t) it++;
    const int jt = t - it * (it + 1) / 2;
    const int h = blockIdx.y;

    __shared__ __align__(16) union SM {
        struct { float Kn[64][32]; float Vs[64][32]; float sK[64]; } a;
        struct { float red[4][64][33]; float redden[4][64]; } b;
    } sm;

    const int tid = threadIdx.x;
    const int ti = tid & 63;           // query row within tile
    const int tg = tid >> 6;           // 0..3, 4-way split over j

    // load K (negated) and V tiles
#pragma unroll
    for (int l = 0; l < 2; l++) {
        int f = tid + l * 256;
        int r = f >> 3;
        int c4 = (f & 7) << 2;
        float4 kv = *(const float4*)&g_K[(jt * 64 + r) * DM + h * DU + c4];
        kv.x = -kv.x; kv.y = -kv.y; kv.z = -kv.z; kv.w = -kv.w;
        *(float4*)&sm.a.Kn[r][c4] = kv;
        *(float4*)&sm.a.Vs[r][c4] = *(const float4*)&g_V[(jt * 64 + r) * DM + h * DU + c4];
    }
    if (tid < 64) sm.a.sK[tid] = g_sumK[h * S_LEN + jt * 64 + tid];

    const int ig = it * 64 + ti;
    uint64_t qp[16];
    {
        const ulonglong2* qg = (const ulonglong2*)&g_Q[ig * DM + h * DU];
#pragma unroll
        for (int c = 0; c < 8; c++) { ulonglong2 u = qg[c]; qp[2 * c] = u.x; qp[2 * c + 1] = u.y; }
    }
    __syncthreads();

    uint64_t acc[16];
#pragma unroll
    for (int c = 0; c < 16; c++) acc[c] = 0;
    float den = 0.f;
    const uint64_t AMASK = 0x7FFFFFFF7FFFFFFFULL;

    // lambda (not a macro!) so there is no identifier shadowing hazard
    auto jbody = [&](int jl) {
        const ulonglong2* kr = (const ulonglong2*)&sm.a.Kn[jl][0];
        uint64_t s0 = 0, s1 = 0;
#pragma unroll
        for (int c = 0; c < 8; c++) {
            ulonglong2 kc = kr[c];
            uint64_t t0 = f32x2_add(qp[2 * c], kc.x) & AMASK;       // FADD2 + 2xLOP3
            uint64_t t1 = f32x2_add(qp[2 * c + 1], kc.y) & AMASK;
            s0 = f32x2_add(s0, t0);
            s1 = f32x2_add(s1, t1);
        }
        float2 u0 = f32x2_unpack(s0), u1 = f32x2_unpack(s1);
        float s = (u0.x + u0.y) + (u1.x + u1.y);
        float p = __expf(TEMPC * (sm.a.sK[jl] - s));
        den += p;
        uint64_t pp = f32x2_pack(p, p);
        const ulonglong2* vr = (const ulonglong2*)&sm.a.Vs[jl][0];
#pragma unroll
        for (int c = 0; c < 8; c++) {
            ulonglong2 vc = vr[c];
            acc[2 * c]     = f32x2_fma(pp, vc.x, acc[2 * c]);       // FFMA2
            acc[2 * c + 1] = f32x2_fma(pp, vc.y, acc[2 * c + 1]);
        }
    };

    if (it != jt) {
#pragma unroll 2
        for (int jj = 0; jj < 16; jj++) jbody((jj << 2) + tg);
    } else {
#pragma unroll 2
        for (int jj = 0; jj < 16; jj++) {
            int jl = (jj << 2) + tg;
            if (jl <= ti) jbody(jl);      // causal (diagonal tile only)
        }
    }

    __syncthreads();   // all warps done with Kn/Vs before overlay write
#pragma unroll
    for (int c = 0; c < 16; c++) {
        float2 u = f32x2_unpack(acc[c]);
        sm.b.red[tg][ti][2 * c]     = u.x;
        sm.b.red[tg][ti][2 * c + 1] = u.y;
    }
    sm.b.redden[tg][ti] = den;
    __syncthreads();

    const int i2 = tid >> 2;       // 0..63
    const int dg = tid & 3;        // 8 d's each
    const int base = dg * 8;
    const int gi = it * 64 + i2;
    float outv[8];
#pragma unroll
    for (int dd = 0; dd < 8; dd++)
        outv[dd] = (sm.b.red[0][i2][base + dd] + sm.b.red[1][i2][base + dd]) +
                   (sm.b.red[2][i2][base + dd] + sm.b.red[3][i2][base + dd]);

    float* np = &g_pnum[(((size_t)jt * NH + h) * S_LEN + gi) * DU + base];
    *(float4*)&np[0] = make_float4(outv[0], outv[1], outv[2], outv[3]);
    *(float4*)&np[4] = make_float4(outv[4], outv[5], outv[6], outv[7]);
    if (dg == 0)
        g_pden[((size_t)jt * NH + h) * S_LEN + gi] =
            (sm.b.redden[0][i2] + sm.b.redden[1][i2]) +
            (sm.b.redden[2][i2] + sm.b.redden[3][i2]);
}

// ---------------- combine partials (4-way jt split + shfl), write O --------
__global__ __launch_bounds__(256) void reduce_kernel()
{
    int gidx = blockIdx.x * 256 + threadIdx.x;          // 1,048,576 threads
    int sp = (gidx >> 3) & 3;                           // jt split 0..3
    int os = ((gidx >> 5) << 3) + (gidx & 7);           // scalar output index
    int i = os >> 8;
    int col = os & 255;
    int h = col >> 5;
    int d = col & 31;
    int it = i >> 6;
    const float* pn = &g_pnum[((size_t)h * S_LEN + i) * DU + d];
    const float* pd = &g_pden[(size_t)h * S_LEN + i];
    const size_t sj = (size_t)NH * S_LEN * DU;
    const size_t sd = (size_t)NH * S_LEN;
    float num = 0.f, den = 0.f;
#pragma unroll 4
    for (int jt = sp; jt <= it; jt += 4) {
        num += pn[(size_t)jt * sj];
        den += pd[(size_t)jt * sd];
    }
    num += __shfl_xor_sync(0xFFFFFFFFu, num, 8);
    den += __shfl_xor_sync(0xFFFFFFFFu, den, 8);
    num += __shfl_xor_sync(0xFFFFFFFFu, num, 16);
    den += __shfl_xor_sync(0xFFFFFFFFu, den, 16);
    if (sp == 0)
        g_O[i * DM + col] = num / den;
}

// ---------------- launch ----------------
extern "C" void kernel_launch(void* const* d_in, const int* in_sizes, int n_in,
                              void* d_out, int out_size)
{
    const float* x  = (const float*)d_in[0];
    const float* Wq = (const float*)d_in[1];
    const float* bq = (const float*)d_in[2];
    const float* Wk = (const float*)d_in[3];
    const float* bk = (const float*)d_in[4];
    const float* Wv = (const float*)d_in[5];
    const float* bv = (const float*)d_in[6];
    const float* Wo = (const float*)d_in[7];
    const float* bo = (const float*)d_in[8];
    float* out = (float*)d_out;

    qkv_kernel<<<dim3(32, 4, 3), 256>>>(x, Wq, bq, Wk, bk, Wv, bv);
    attn_kernel<<<dim3(136, 8), 256>>>();
    reduce_kernel<<<4096, 256>>>();
    proj_kernel<<<dim3(32, 4, 1), 256>>>(Wo, bo, out);
}

// round 8
// speedup vs baseline: 1.7661x; 1.7661x over previous
#include <cuda_runtime.h>
#include <cstdint>

#define S_LEN 1024
#define DM 256
#define NH 8
#define DU 32
#define NT 16               // S_LEN / 64
#define TEMPC 0.078125f     // TEMP / (2*DU) = 5/64

// ---------------- scratch (no allocations allowed) ----------------
__device__ float g_Q[S_LEN * DM];
__device__ float g_K[S_LEN * DM];
__device__ float g_V[S_LEN * DM];
__device__ float g_O[S_LEN * DM];
__device__ float g_sumK[NH * S_LEN];
__device__ float g_pnum[NT * NH * S_LEN * DU];   // [jt][h][i][d]
__device__ float g_pden[NT * NH * S_LEN];        // [jt][h][i]
__device__ float g_Pp[2 * S_LEN * DM];           // proj k-split partials

// ---------------- packed f32x2 helpers (attn only) ----------------
__device__ __forceinline__ uint64_t f32x2_add(uint64_t a, uint64_t b) {
    uint64_t d; asm("add.rn.f32x2 %0, %1, %2;" : "=l"(d) : "l"(a), "l"(b)); return d;
}
__device__ __forceinline__ uint64_t f32x2_fma(uint64_t a, uint64_t b, uint64_t c) {
    uint64_t d; asm("fma.rn.f32x2 %0, %1, %2, %3;" : "=l"(d) : "l"(a), "l"(b), "l"(c)); return d;
}
__device__ __forceinline__ uint64_t f32x2_pack(float x, float y) {
    uint64_t d; asm("mov.b64 %0, {%1, %2};" : "=l"(d) : "f"(x), "f"(y)); return d;
}
__device__ __forceinline__ float2 f32x2_unpack(uint64_t a) {
    float2 r; asm("mov.b64 {%0, %1}, %2;" : "=f"(r.x), "=f"(r.y) : "l"(a)); return r;
}

// ---------------- 32x64-tile fp32 GEMM, 128 threads, 4m x 4n/thread ------
// 1 B smem per FMA-lane: crossbar and fma pipe balanced.
// SUMK: also emit per-row per-head sums of the activated outputs
//       (tile n-halves are whole heads).  PARTIAL: no bias, raw partial store.
template<bool SIG, bool SUMK, bool PARTIAL>
__device__ __forceinline__ void gemm32(const float* __restrict__ A,
                                       const float* __restrict__ W,
                                       const float* __restrict__ b,
                                       float* __restrict__ C,
                                       float* __restrict__ sumk,
                                       int bm, int bn, int kstart, int kend)
{
    __shared__ __align__(16) float Ast[32][36];   // [k][m], 144B row (16B-mult)
    __shared__ __align__(16) float Ws[32][64];    // [k][n]
    __shared__ float ssum[32][16];

    const int tid = threadIdx.x;      // 0..127
    const int tx = tid & 15;          // n = tx*4..+3
    const int ty = tid >> 4;          // m = ty*4..+3

    float c[4][4];
#pragma unroll
    for (int m = 0; m < 4; m++)
#pragma unroll
        for (int n = 0; n < 4; n++) c[m][n] = 0.f;

    for (int k0 = kstart; k0 < kend; k0 += 32) {
#pragma unroll
        for (int l = 0; l < 2; l++) {       // A tile 32m x 32k, transposed
            int f = tid + l * 128;
            int m = f >> 3;
            int kc = (f & 7) << 2;
            float4 v = *(const float4*)&A[(bm * 32 + m) * DM + k0 + kc];
            Ast[kc + 0][m] = v.x;
            Ast[kc + 1][m] = v.y;
            Ast[kc + 2][m] = v.z;
            Ast[kc + 3][m] = v.w;
        }
#pragma unroll
        for (int l = 0; l < 4; l++) {       // W tile 32k x 64n
            int f = tid + l * 128;
            int k = f >> 4;
            int nc = (f & 15) << 2;
            *(float4*)&Ws[k][nc] = *(const float4*)&W[(k0 + k) * DM + bn * 64 + nc];
        }
        __syncthreads();
#pragma unroll
        for (int k = 0; k < 32; k++) {
            float4 av = *(const float4*)&Ast[k][ty * 4];
            float4 wv = *(const float4*)&Ws[k][tx * 4];
            float am[4] = {av.x, av.y, av.z, av.w};
            float wn[4] = {wv.x, wv.y, wv.z, wv.w};
#pragma unroll
            for (int m = 0; m < 4; m++)
#pragma unroll
                for (int n = 0; n < 4; n++) c[m][n] += am[m] * wn[n];
        }
        __syncthreads();
    }

    float bb[4] = {0.f, 0.f, 0.f, 0.f};
    if (!PARTIAL) {
        float4 bv = *(const float4*)&b[bn * 64 + tx * 4];
        bb[0] = bv.x; bb[1] = bv.y; bb[2] = bv.z; bb[3] = bv.w;
    }
    float rs[4];
#pragma unroll
    for (int m = 0; m < 4; m++) {
        float t[4];
#pragma unroll
        for (int n = 0; n < 4; n++) {
            float v = c[m][n] + bb[n];
            if (SIG) v = 1.0f / (1.0f + __expf(-v));
            t[n] = v;
        }
        if (SUMK) rs[m] = (t[0] + t[1]) + (t[2] + t[3]);
        *(float4*)&C[(bm * 32 + ty * 4 + m) * DM + bn * 64 + tx * 4] =
            make_float4(t[0], t[1], t[2], t[3]);
    }

    if (SUMK) {
#pragma unroll
        for (int m = 0; m < 4; m++) ssum[ty * 4 + m][tx] = rs[m];
        __syncthreads();
        if (tid < 64) {
            int m = tid >> 1, half = tid & 1;
            float s = 0.f;
#pragma unroll
            for (int x = 0; x < 8; x++) s += ssum[m][half * 8 + x];
            sumk[(bn * 2 + half) * S_LEN + bm * 32 + m] = s;
        }
    }
}

__global__ __launch_bounds__(128) void qkv_kernel(const float* __restrict__ x,
                                                  const float* __restrict__ Wq, const float* __restrict__ bq,
                                                  const float* __restrict__ Wk, const float* __restrict__ bk,
                                                  const float* __restrict__ Wv, const float* __restrict__ bv)
{
    int z = blockIdx.z;
    if (z == 0)      gemm32<true,  false, false>(x, Wq, bq, g_Q, nullptr, blockIdx.x, blockIdx.y, 0, DM);
    else if (z == 1) gemm32<true,  true,  false>(x, Wk, bk, g_K, g_sumK,  blockIdx.x, blockIdx.y, 0, DM);
    else             gemm32<false, false, false>(x, Wv, bv, g_V, nullptr, blockIdx.x, blockIdx.y, 0, DM);
}

// proj: k-split 2 -> partials in g_Pp (deterministic, no atomics)
__global__ __launch_bounds__(128) void proj_kernel(const float* __restrict__ Wo)
{
    int z = blockIdx.z;
    gemm32<false, false, true>(g_O, Wo, nullptr, g_Pp + (size_t)z * S_LEN * DM,
                               nullptr, blockIdx.x, blockIdx.y, z * 128, z * 128 + 128);
}

__global__ __launch_bounds__(256) void combine_kernel(const float* __restrict__ bo,
                                                      float* __restrict__ out)
{
    int idx = blockIdx.x * 256 + threadIdx.x;   // 65536 float4s
    int i = idx >> 6;
    int c4 = (idx & 63) << 2;
    float4 a = *(const float4*)&g_Pp[(size_t)i * DM + c4];
    float4 p = *(const float4*)&g_Pp[(size_t)S_LEN * DM + (size_t)i * DM + c4];
    float4 bv = *(const float4*)&bo[c4];
    *(float4*)&out[(size_t)i * DM + c4] =
        make_float4(a.x + p.x + bv.x, a.y + p.y + bv.y,
                    a.z + p.z + bv.z, a.w + p.w + bv.w);
}

// ---------------- attention tile kernel (packed f32x2) ----------------
// p_ij = exp( TEMPC * (sumK_j - sum_d |Q_id - K_jd|) ); row-const terms cancel.
// Grid.x enumerates the 136 lower-triangle (it,jt) tiles exactly.
__global__ __launch_bounds__(256) void attn_kernel()
{
    // decode triangular index -> (it, jt)
    int t = blockIdx.x;
    int it = (int)((sqrtf(8.0f * t + 1.0f) - 1.0f) * 0.5f);
    if ((it + 1) * (it + 2) / 2 <= t) it++;
    const int jt = t - it * (it + 1) / 2;
    const int h = blockIdx.y;

    __shared__ __align__(16) union SM {
        struct { float Kn[64][32]; float Vs[64][32]; float sK[64]; } a;
        struct { float red[4][64][33]; float redden[4][64]; } b;
    } sm;

    const int tid = threadIdx.x;
    const int ti = tid & 63;           // query row within tile
    const int tg = tid >> 6;           // 0..3, 4-way split over j

    // load K (negated) and V tiles
#pragma unroll
    for (int l = 0; l < 2; l++) {
        int f = tid + l * 256;
        int r = f >> 3;
        int c4 = (f & 7) << 2;
        float4 kv = *(const float4*)&g_K[(jt * 64 + r) * DM + h * DU + c4];
        kv.x = -kv.x; kv.y = -kv.y; kv.z = -kv.z; kv.w = -kv.w;
        *(float4*)&sm.a.Kn[r][c4] = kv;
        *(float4*)&sm.a.Vs[r][c4] = *(const float4*)&g_V[(jt * 64 + r) * DM + h * DU + c4];
    }
    if (tid < 64) sm.a.sK[tid] = g_sumK[h * S_LEN + jt * 64 + tid];

    const int ig = it * 64 + ti;
    uint64_t qp[16];
    {
        const ulonglong2* qg = (const ulonglong2*)&g_Q[ig * DM + h * DU];
#pragma unroll
        for (int c = 0; c < 8; c++) { ulonglong2 u = qg[c]; qp[2 * c] = u.x; qp[2 * c + 1] = u.y; }
    }
    __syncthreads();

    uint64_t acc[16];
#pragma unroll
    for (int c = 0; c < 16; c++) acc[c] = 0;
    float den = 0.f;
    const uint64_t AMASK = 0x7FFFFFFF7FFFFFFFULL;

    // lambda (not a macro) - no identifier shadowing hazard
    auto jbody = [&](int jl) {
        const ulonglong2* kr = (const ulonglong2*)&sm.a.Kn[jl][0];
        uint64_t s0 = 0, s1 = 0;
#pragma unroll
        for (int c = 0; c < 8; c++) {
            ulonglong2 kc = kr[c];
            uint64_t t0 = f32x2_add(qp[2 * c], kc.x) & AMASK;       // FADD2 + 2xLOP3
            uint64_t t1 = f32x2_add(qp[2 * c + 1], kc.y) & AMASK;
            s0 = f32x2_add(s0, t0);
            s1 = f32x2_add(s1, t1);
        }
        float2 u0 = f32x2_unpack(s0), u1 = f32x2_unpack(s1);
        float s = (u0.x + u0.y) + (u1.x + u1.y);
        float p = __expf(TEMPC * (sm.a.sK[jl] - s));
        den += p;
        uint64_t pp = f32x2_pack(p, p);
        const ulonglong2* vr = (const ulonglong2*)&sm.a.Vs[jl][0];
#pragma unroll
        for (int c = 0; c < 8; c++) {
            ulonglong2 vc = vr[c];
            acc[2 * c]     = f32x2_fma(pp, vc.x, acc[2 * c]);       // FFMA2
            acc[2 * c + 1] = f32x2_fma(pp, vc.y, acc[2 * c + 1]);
        }
    };

    if (it != jt) {
#pragma unroll 2
        for (int jj = 0; jj < 16; jj++) jbody((jj << 2) + tg);
    } else {
#pragma unroll 2
        for (int jj = 0; jj < 16; jj++) {
            int jl = (jj << 2) + tg;
            if (jl <= ti) jbody(jl);      // causal (diagonal tile only)
        }
    }

    __syncthreads();   // all warps done with Kn/Vs before overlay write
#pragma unroll
    for (int c = 0; c < 16; c++) {
        float2 u = f32x2_unpack(acc[c]);
        sm.b.red[tg][ti][2 * c]     = u.x;
        sm.b.red[tg][ti][2 * c + 1] = u.y;
    }
    sm.b.redden[tg][ti] = den;
    __syncthreads();

    const int i2 = tid >> 2;       // 0..63
    const int dg = tid & 3;        // 8 d's each
    const int base = dg * 8;
    const int gi = it * 64 + i2;
    float outv[8];
#pragma unroll
    for (int dd = 0; dd < 8; dd++)
        outv[dd] = (sm.b.red[0][i2][base + dd] + sm.b.red[1][i2][base + dd]) +
                   (sm.b.red[2][i2][base + dd] + sm.b.red[3][i2][base + dd]);

    float* np = &g_pnum[(((size_t)jt * NH + h) * S_LEN + gi) * DU + base];
    *(float4*)&np[0] = make_float4(outv[0], outv[1], outv[2], outv[3]);
    *(float4*)&np[4] = make_float4(outv[4], outv[5], outv[6], outv[7]);
    if (dg == 0)
        g_pden[((size_t)jt * NH + h) * S_LEN + gi] =
            (sm.b.redden[0][i2] + sm.b.redden[1][i2]) +
            (sm.b.redden[2][i2] + sm.b.redden[3][i2]);
}

// ---------------- combine partials (4-way jt split + shfl), write O --------
__global__ __launch_bounds__(256) void reduce_kernel()
{
    int gidx = blockIdx.x * 256 + threadIdx.x;          // 1,048,576 threads
    int sp = (gidx >> 3) & 3;                           // jt split 0..3
    int os = ((gidx >> 5) << 3) + (gidx & 7);           // scalar output index
    int i = os >> 8;
    int col = os & 255;
    int h = col >> 5;
    int d = col & 31;
    int it = i >> 6;
    const float* pn = &g_pnum[((size_t)h * S_LEN + i) * DU + d];
    const float* pd = &g_pden[(size_t)h * S_LEN + i];
    const size_t sj = (size_t)NH * S_LEN * DU;
    const size_t sd = (size_t)NH * S_LEN;
    float num = 0.f, den = 0.f;
#pragma unroll 4
    for (int jt = sp; jt <= it; jt += 4) {
        num += pn[(size_t)jt * sj];
        den += pd[(size_t)jt * sd];
    }
    num += __shfl_xor_sync(0xFFFFFFFFu, num, 8);
    den += __shfl_xor_sync(0xFFFFFFFFu, den, 8);
    num += __shfl_xor_sync(0xFFFFFFFFu, num, 16);
    den += __shfl_xor_sync(0xFFFFFFFFu, den, 16);
    if (sp == 0)
        g_O[i * DM + col] = num / den;
}

// ---------------- launch ----------------
extern "C" void kernel_launch(void* const* d_in, const int* in_sizes, int n_in,
                              void* d_out, int out_size)
{
    const float* x  = (const float*)d_in[0];
    const float* Wq = (const float*)d_in[1];
    const float* bq = (const float*)d_in[2];
    const float* Wk = (const float*)d_in[3];
    const float* bk = (const float*)d_in[4];
    const float* Wv = (const float*)d_in[5];
    const float* bv = (const float*)d_in[6];
    const float* Wo = (const float*)d_in[7];
    const float* bo = (const float*)d_in[8];
    float* out = (float*)d_out;

    qkv_kernel<<<dim3(32, 4, 3), 128>>>(x, Wq, bq, Wk, bk, Wv, bv);
    attn_kernel<<<dim3(136, 8), 256>>>();
    reduce_kernel<<<4096, 256>>>();
    proj_kernel<<<dim3(32, 4, 2), 128>>>(Wo);
    combine_kernel<<<256, 256>>>(bo, out);
}